// round 11
// baseline (speedup 1.0000x reference)
#include <cuda_runtime.h>
#include <cstddef>

// Problem constants (fixed shapes)
#define NB 8    // batch
#define NH 4    // batches per group (2 groups, overlapped via streams)
#define CC 8    // channels
#define TT 600  // time frames
#define FF 513  // freq bins
#define TS 20   // T-split chunks (<= 32 for the warp-reduce)
#define TCH (TT / TS)       // 30 frames per chunk
#define NP 16               // partial entries: 8 re(nume) + 8 im(nume)

__device__ float g_part[(size_t)TS * NB * NP * FF];  // ~5.3 MB partials
__device__ float g_w[(size_t)NB * CC * 2 * FF];      // conj(w), [n][c][re/im][f]

// ---------------------------------------------------------------------------
// Kernel 1: partial nume_c = sum_t x_c * s_t, with s_t = sum_e conj(x_e) d_e.
// (best measured form: depth-1 prefetch, plain LDG, TS=20)
// grid: (ceil(NH*FF/128), TS), block 128. Covers batches [n0, n0+NH).
// ---------------------------------------------------------------------------
__global__ void snum_kernel(const float* __restrict__ x,
                            const float* __restrict__ sv, int n0) {
    int id = blockIdx.x * 128 + threadIdx.x;  // over NH*FF
    int z = blockIdx.y;
    if (id >= NH * FF) return;
    int n = n0 + id / FF;
    int f = id % FF;

    // steering vector d[f][c], layout [2, F, C, 1]
    float dr[CC], di[CC];
#pragma unroll
    for (int c = 0; c < CC; ++c) {
        dr[c] = sv[(size_t)(0 * FF + f) * CC + c];
        di[c] = sv[(size_t)(1 * FF + f) * CC + c];
    }

    float numr[CC], numi[CC];
#pragma unroll
    for (int c = 0; c < CC; ++c) { numr[c] = 0.f; numi[c] = 0.f; }

    const size_t chanStride = (size_t)TT * FF;
    const float* xr = x + (size_t)(n * 2 + 0) * CC * chanStride + f;
    const float* xi = x + (size_t)(n * 2 + 1) * CC * chanStride + f;

    int t0 = z * TCH;
    float a[CC], b[CC];
    {
        size_t toff = (size_t)t0 * FF;
#pragma unroll
        for (int c = 0; c < CC; ++c) {
            a[c] = xr[(size_t)c * chanStride + toff];
            b[c] = xi[(size_t)c * chanStride + toff];
        }
    }

#pragma unroll 2
    for (int i = 0; i < TCH; ++i) {
        float na[CC], nb[CC];
        if (i < TCH - 1) {
            size_t toff2 = (size_t)(t0 + i + 1) * FF;
#pragma unroll
            for (int c = 0; c < CC; ++c) {
                na[c] = xr[(size_t)c * chanStride + toff2];
                nb[c] = xi[(size_t)c * chanStride + toff2];
            }
        }

        // s_t = sum_c conj(x_c) d_c
        float sr = 0.f, si = 0.f;
#pragma unroll
        for (int c = 0; c < CC; ++c) {
            sr += a[c] * dr[c] + b[c] * di[c];
            si += a[c] * di[c] - b[c] * dr[c];
        }
        // nume_c += x_c * s_t
#pragma unroll
        for (int c = 0; c < CC; ++c) {
            numr[c] += a[c] * sr - b[c] * si;
            numi[c] += a[c] * si + b[c] * sr;
        }

        if (i < TCH - 1) {
#pragma unroll
            for (int c = 0; c < CC; ++c) { a[c] = na[c]; b[c] = nb[c]; }
        }
    }

    float* pb = g_part + ((size_t)(z * NB + n) * NP) * FF + f;
#pragma unroll
    for (int c = 0; c < CC; ++c) {
        pb[(size_t)c * FF] = numr[c];
        pb[(size_t)(8 + c) * FF] = numi[c];
    }
}

// ---------------------------------------------------------------------------
// Kernel 2: warp per (n,f). Lane z loads that chunk's 16 partials; butterfly
// shuffle reduction; lane 0 applies loading and solves for conj(w).
// Covers batches [n0, n0+NH).
// ---------------------------------------------------------------------------
__global__ void __launch_bounds__(256) weight_kernel(const float* __restrict__ sv,
                                                     int n0) {
    int gw = (blockIdx.x * 256 + threadIdx.x) >> 5;  // warp id over NH*FF
    int lane = threadIdx.x & 31;
    if (gw >= NH * FF) return;
    int n = n0 + gw / FF;
    int f = gw % FF;

    float v[NP];
    if (lane < TS) {
        const float* pb = g_part + ((size_t)(lane * NB + n) * NP) * FF + f;
#pragma unroll
        for (int k = 0; k < NP; ++k) v[k] = pb[(size_t)k * FF];
    } else {
#pragma unroll
        for (int k = 0; k < NP; ++k) v[k] = 0.f;
    }

#pragma unroll
    for (int off = 16; off >= 1; off >>= 1) {
#pragma unroll
        for (int k = 0; k < NP; ++k)
            v[k] += __shfl_down_sync(0xffffffffu, v[k], off);
    }

    if (lane != 0) return;

    const float invT = 1.0f / (float)TT;
    const float LOADC = 0.001f * 0.7071067811865475f;  // 0.001/sqrt(2)

    float dr[CC], di[CC];
#pragma unroll
    for (int c = 0; c < CC; ++c) {
        dr[c] = sv[(size_t)(0 * FF + f) * CC + c];
        di[c] = sv[(size_t)(1 * FF + f) * CC + c];
    }

    // nume_c = invT*sum + LOAD*(1+i)*d_c
    float nr[CC], ni[CC];
#pragma unroll
    for (int c = 0; c < CC; ++c) {
        nr[c] = v[c] * invT + LOADC * (dr[c] - di[c]);
        ni[c] = v[8 + c] * invT + LOADC * (dr[c] + di[c]);
    }
    // deno = sum_c conj(d_c) * nume_c
    float der = 0.f, dei = 0.f;
#pragma unroll
    for (int c = 0; c < CC; ++c) {
        der += dr[c] * nr[c] + di[c] * ni[c];
        dei += dr[c] * ni[c] - di[c] * nr[c];
    }
    float inv = 1.0f / (der * der + dei * dei);

#pragma unroll
    for (int c = 0; c < CC; ++c) {
        float wr = (nr[c] * der + ni[c] * dei) * inv;
        float wi = (ni[c] * der - nr[c] * dei) * inv;
        g_w[((size_t)(n * CC + c) * 2 + 0) * FF + f] = wr;   // re(conj w)
        g_w[((size_t)(n * CC + c) * 2 + 1) * FF + f] = -wi;  // im(conj w)
    }
}

// ---------------------------------------------------------------------------
// Kernel 3: beamform mixture with conj(w). Depth-2 software pipeline +
// streaming hints. grid: (ceil(F/128), T/TB, NH) with batch offset n0.
// ---------------------------------------------------------------------------
#define TB 8
__global__ void bf_kernel(const float* __restrict__ y,
                          float* __restrict__ out, int n0) {
    int f = blockIdx.x * 128 + threadIdx.x;
    int n = n0 + blockIdx.z;
    int t0 = blockIdx.y * TB;
    if (f >= FF) return;

    float cwr[CC], cwi[CC];
#pragma unroll
    for (int c = 0; c < CC; ++c) {
        cwr[c] = g_w[((size_t)(n * CC + c) * 2 + 0) * FF + f];
        cwi[c] = g_w[((size_t)(n * CC + c) * 2 + 1) * FF + f];
    }

    const size_t chanStride = (size_t)TT * FF;
    const float* yr = y + (size_t)(n * 2 + 0) * CC * chanStride + f;
    const float* yi = y + (size_t)(n * 2 + 1) * CC * chanStride + f;
    float* outr = out + (size_t)(n * 2 + 0) * TT * FF + f;
    float* outi = out + (size_t)(n * 2 + 1) * TT * FF + f;

    float a[2][CC], b[2][CC];
#pragma unroll
    for (int s = 0; s < 2; ++s) {
        size_t toff = (size_t)(t0 + s) * FF;
#pragma unroll
        for (int c = 0; c < CC; ++c) {
            a[s][c] = __ldcs(yr + (size_t)c * chanStride + toff);
            b[s][c] = __ldcs(yi + (size_t)c * chanStride + toff);
        }
    }

#pragma unroll
    for (int i = 0; i < TB; ++i) {
        const int s = i & 1;
        float na[CC], nb[CC];
        if (i < TB - 2) {
            size_t toff2 = (size_t)(t0 + i + 2) * FF;
#pragma unroll
            for (int c = 0; c < CC; ++c) {
                na[c] = __ldcs(yr + (size_t)c * chanStride + toff2);
                nb[c] = __ldcs(yi + (size_t)c * chanStride + toff2);
            }
        }

        float ar = 0.f, ai = 0.f;
#pragma unroll
        for (int c = 0; c < CC; ++c) {
            ar += cwr[c] * a[s][c] - cwi[c] * b[s][c];
            ai += cwr[c] * b[s][c] + cwi[c] * a[s][c];
        }
        size_t toff = (size_t)(t0 + i) * FF;
        __stcs(outr + toff, ar);
        __stcs(outi + toff, ai);

        if (i < TB - 2) {
#pragma unroll
            for (int c = 0; c < CC; ++c) { a[s][c] = na[c]; b[s][c] = nb[c]; }
        }
    }
}

extern "C" void kernel_launch(void* const* d_in, const int* in_sizes, int n_in,
                              void* d_out, int out_size) {
    const float* mixture = (const float*)d_in[0];
    // d_in[1] = noise (unused by the reference computation)
    const float* target = (const float*)d_in[2];
    const float* sv = (const float*)d_in[3];
    float* out = (float*)d_out;

    // Lazily created once (first call runs outside graph capture); reused on
    // the capture call so the capture path contains no resource creation.
    static cudaStream_t s2 = nullptr;
    static cudaEvent_t ev0 = nullptr, ev2 = nullptr;
    if (s2 == nullptr) {
        cudaStreamCreateWithFlags(&s2, cudaStreamNonBlocking);
        cudaEventCreateWithFlags(&ev0, cudaEventDisableTiming);
        cudaEventCreateWithFlags(&ev2, cudaEventDisableTiming);
    }

    const int nth = NH * FF;                         // 2052 per group
    dim3 gS((nth + 127) / 128, TS);                  // snum grid per group
    int gW = (nth * 32 + 255) / 256;                 // weight grid per group
    dim3 gB((FF + 127) / 128, TT / TB, NH);          // bf grid per group

    // Stream 0 (capture origin): snum(g0) -> ev0 -> snum(g1)
    snum_kernel<<<gS, 128>>>(target, sv, 0);
    cudaEventRecord(ev0, 0);
    snum_kernel<<<gS, 128>>>(target, sv, NH);

    // Stream s2: after snum(g0): weight(g0) -> bf(g0)  [overlaps snum(g1)]
    cudaStreamWaitEvent(s2, ev0, 0);
    weight_kernel<<<gW, 256, 0, s2>>>(sv, 0);
    bf_kernel<<<gB, 128, 0, s2>>>(mixture, out, 0);
    cudaEventRecord(ev2, s2);

    // Stream 0: join, then weight(g1) -> bf(g1)
    cudaStreamWaitEvent(0, ev2, 0);
    weight_kernel<<<gW, 256>>>(sv, NH);
    bf_kernel<<<gB, 128>>>(mixture, out, NH);
}

// round 12
// speedup vs baseline: 1.2442x; 1.2442x over previous
#include <cuda_runtime.h>
#include <cstddef>

// Problem constants (fixed shapes)
#define NB 8    // batch
#define CC 8    // channels
#define TT 600  // time frames
#define FF 513  // freq bins
#define TS 20   // T-split chunks (<= 32 for the warp-reduce)
#define TCH (TT / TS)       // 30 frames per chunk
#define NP 16               // partial entries: 8 re(nume) + 8 im(nume)

__device__ float g_part[(size_t)TS * NB * NP * FF];  // ~5.3 MB partials
__device__ float g_w[(size_t)NB * CC * 2 * FF];      // conj(w), [n][c][re/im][f]

// ---------------------------------------------------------------------------
// Kernel 1: partial nume_c = sum_t x_c * s_t, with s_t = sum_e conj(x_e) d_e.
// (measured-best form: depth-1 prefetch, plain LDG, TS=20)
// grid: (ceil(NB*FF/128), TS), block 128.
// ---------------------------------------------------------------------------
__global__ void snum_kernel(const float* __restrict__ x,
                            const float* __restrict__ sv) {
    int id = blockIdx.x * 128 + threadIdx.x;  // over NB*FF
    int z = blockIdx.y;
    if (id >= NB * FF) return;
    int n = id / FF;
    int f = id - n * FF;

    // steering vector d[f][c], layout [2, F, C, 1]
    float dr[CC], di[CC];
#pragma unroll
    for (int c = 0; c < CC; ++c) {
        dr[c] = sv[(size_t)(0 * FF + f) * CC + c];
        di[c] = sv[(size_t)(1 * FF + f) * CC + c];
    }

    float numr[CC], numi[CC];
#pragma unroll
    for (int c = 0; c < CC; ++c) { numr[c] = 0.f; numi[c] = 0.f; }

    const size_t chanStride = (size_t)TT * FF;
    const float* xr = x + (size_t)(n * 2 + 0) * CC * chanStride + f;
    const float* xi = x + (size_t)(n * 2 + 1) * CC * chanStride + f;

    int t0 = z * TCH;
    float a[CC], b[CC];
    {
        size_t toff = (size_t)t0 * FF;
#pragma unroll
        for (int c = 0; c < CC; ++c) {
            a[c] = xr[(size_t)c * chanStride + toff];
            b[c] = xi[(size_t)c * chanStride + toff];
        }
    }

#pragma unroll 2
    for (int i = 0; i < TCH; ++i) {
        float na[CC], nb[CC];
        if (i < TCH - 1) {
            size_t toff2 = (size_t)(t0 + i + 1) * FF;
#pragma unroll
            for (int c = 0; c < CC; ++c) {
                na[c] = xr[(size_t)c * chanStride + toff2];
                nb[c] = xi[(size_t)c * chanStride + toff2];
            }
        }

        // s_t = sum_c conj(x_c) d_c
        float sr = 0.f, si = 0.f;
#pragma unroll
        for (int c = 0; c < CC; ++c) {
            sr += a[c] * dr[c] + b[c] * di[c];
            si += a[c] * di[c] - b[c] * dr[c];
        }
        // nume_c += x_c * s_t
#pragma unroll
        for (int c = 0; c < CC; ++c) {
            numr[c] += a[c] * sr - b[c] * si;
            numi[c] += a[c] * si + b[c] * sr;
        }

        if (i < TCH - 1) {
#pragma unroll
            for (int c = 0; c < CC; ++c) { a[c] = na[c]; b[c] = nb[c]; }
        }
    }

    float* pb = g_part + ((size_t)(z * NB + n) * NP) * FF + f;
#pragma unroll
    for (int c = 0; c < CC; ++c) {
        pb[(size_t)c * FF] = numr[c];
        pb[(size_t)(8 + c) * FF] = numi[c];
    }

    // PDL: allow the dependent weight kernel's sync to release as soon as all
    // snum blocks have passed this point.
    cudaTriggerProgrammaticLaunchCompletion();
}

// ---------------------------------------------------------------------------
// Kernel 2: warp per (n,f). Lane z loads that chunk's 16 partials; butterfly
// shuffle reduction; lane 0 applies loading and solves for conj(w).
// Launched with PDL serialization against snum; loads sv (independent input)
// before the dependency sync. grid is exactly 513 blocks (no invalid warps).
// ---------------------------------------------------------------------------
__global__ void __launch_bounds__(256) weight_kernel(const float* __restrict__ sv) {
    int gw = (blockIdx.x * 256 + threadIdx.x) >> 5;  // global warp id, < NB*FF
    int lane = threadIdx.x & 31;
    int n = gw / FF;
    int f = gw - n * FF;

    // Independent of snum's output: start these loads before the sync.
    float dr[CC], di[CC];
#pragma unroll
    for (int c = 0; c < CC; ++c) {
        dr[c] = sv[(size_t)(0 * FF + f) * CC + c];
        di[c] = sv[(size_t)(1 * FF + f) * CC + c];
    }

    cudaGridDependencySynchronize();

    float v[NP];
    if (lane < TS) {
        const float* pb = g_part + ((size_t)(lane * NB + n) * NP) * FF + f;
#pragma unroll
        for (int k = 0; k < NP; ++k) v[k] = pb[(size_t)k * FF];
    } else {
#pragma unroll
        for (int k = 0; k < NP; ++k) v[k] = 0.f;
    }

#pragma unroll
    for (int off = 16; off >= 1; off >>= 1) {
#pragma unroll
        for (int k = 0; k < NP; ++k)
            v[k] += __shfl_down_sync(0xffffffffu, v[k], off);
    }

    if (lane == 0) {
        const float invT = 1.0f / (float)TT;
        const float LOADC = 0.001f * 0.7071067811865475f;  // 0.001/sqrt(2)

        // nume_c = invT*sum + LOAD*(1+i)*d_c
        float nr[CC], ni[CC];
#pragma unroll
        for (int c = 0; c < CC; ++c) {
            nr[c] = v[c] * invT + LOADC * (dr[c] - di[c]);
            ni[c] = v[8 + c] * invT + LOADC * (dr[c] + di[c]);
        }
        // deno = sum_c conj(d_c) * nume_c
        float der = 0.f, dei = 0.f;
#pragma unroll
        for (int c = 0; c < CC; ++c) {
            der += dr[c] * nr[c] + di[c] * ni[c];
            dei += dr[c] * ni[c] - di[c] * nr[c];
        }
        float inv = 1.0f / (der * der + dei * dei);

#pragma unroll
        for (int c = 0; c < CC; ++c) {
            float wr = (nr[c] * der + ni[c] * dei) * inv;
            float wi = (ni[c] * der - nr[c] * dei) * inv;
            g_w[((size_t)(n * CC + c) * 2 + 0) * FF + f] = wr;   // re(conj w)
            g_w[((size_t)(n * CC + c) * 2 + 1) * FF + f] = -wi;  // im(conj w)
        }
    }

    cudaTriggerProgrammaticLaunchCompletion();
}

// ---------------------------------------------------------------------------
// Kernel 3: beamform mixture with conj(w). Depth-2 software pipeline.
// Launched with PDL serialization against weight; prefetches its first two
// t's of mixture (independent of w) BEFORE the dependency sync, so the memory
// ramp overlaps weight's execution and snum's tail wave.
// grid: (ceil(F/128), T/TB, N), block 128.
// ---------------------------------------------------------------------------
#define TB 8
__global__ void bf_kernel(const float* __restrict__ y,
                          float* __restrict__ out) {
    int f = blockIdx.x * 128 + threadIdx.x;
    int n = blockIdx.z;
    int t0 = blockIdx.y * TB;
    bool valid = (f < FF);
    int fc = valid ? f : (FF - 1);

    const size_t chanStride = (size_t)TT * FF;
    const float* yr = y + (size_t)(n * 2 + 0) * CC * chanStride + fc;
    const float* yi = y + (size_t)(n * 2 + 1) * CC * chanStride + fc;

    // Prefetch first two t's of mixture before waiting on weight.
    float a[2][CC], b[2][CC];
#pragma unroll
    for (int s = 0; s < 2; ++s) {
        size_t toff = (size_t)(t0 + s) * FF;
#pragma unroll
        for (int c = 0; c < CC; ++c) {
            a[s][c] = __ldcs(yr + (size_t)c * chanStride + toff);
            b[s][c] = __ldcs(yi + (size_t)c * chanStride + toff);
        }
    }

    cudaGridDependencySynchronize();
    if (!valid) return;

    float cwr[CC], cwi[CC];
#pragma unroll
    for (int c = 0; c < CC; ++c) {
        cwr[c] = g_w[((size_t)(n * CC + c) * 2 + 0) * FF + f];
        cwi[c] = g_w[((size_t)(n * CC + c) * 2 + 1) * FF + f];
    }

    float* outr = out + (size_t)(n * 2 + 0) * TT * FF + f;
    float* outi = out + (size_t)(n * 2 + 1) * TT * FF + f;

#pragma unroll
    for (int i = 0; i < TB; ++i) {
        const int s = i & 1;
        float na[CC], nb[CC];
        if (i < TB - 2) {
            size_t toff2 = (size_t)(t0 + i + 2) * FF;
#pragma unroll
            for (int c = 0; c < CC; ++c) {
                na[c] = __ldcs(yr + (size_t)c * chanStride + toff2);
                nb[c] = __ldcs(yi + (size_t)c * chanStride + toff2);
            }
        }

        float ar = 0.f, ai = 0.f;
#pragma unroll
        for (int c = 0; c < CC; ++c) {
            ar += cwr[c] * a[s][c] - cwi[c] * b[s][c];
            ai += cwr[c] * b[s][c] + cwi[c] * a[s][c];
        }
        size_t toff = (size_t)(t0 + i) * FF;
        __stcs(outr + toff, ar);
        __stcs(outi + toff, ai);

        if (i < TB - 2) {
#pragma unroll
            for (int c = 0; c < CC; ++c) { a[s][c] = na[c]; b[s][c] = nb[c]; }
        }
    }
}

extern "C" void kernel_launch(void* const* d_in, const int* in_sizes, int n_in,
                              void* d_out, int out_size) {
    const float* mixture = (const float*)d_in[0];
    // d_in[1] = noise (unused by the reference computation)
    const float* target = (const float*)d_in[2];
    const float* sv = (const float*)d_in[3];
    float* out = (float*)d_out;

    const int nth = NB * FF;  // 4104

    // Kernel 1: plain launch.
    dim3 gA((nth + 127) / 128, TS);
    snum_kernel<<<gA, 128>>>(target, sv);

    // Kernels 2 & 3: programmatic dependent launch (overlap with predecessor
    // tail; each kernel gates its dependent reads with GridDependencySync).
    cudaLaunchAttribute attr[1];
    attr[0].id = cudaLaunchAttributeProgrammaticStreamSerialization;
    attr[0].val.programmaticStreamSerializationAllowed = 1;

    {
        cudaLaunchConfig_t cfg = {};
        cfg.gridDim = dim3((nth * 32 + 255) / 256);  // 513 blocks exactly
        cfg.blockDim = dim3(256);
        cfg.stream = 0;
        cfg.attrs = attr;
        cfg.numAttrs = 1;
        cudaLaunchKernelEx(&cfg, weight_kernel, sv);
    }
    {
        cudaLaunchConfig_t cfg = {};
        cfg.gridDim = dim3((FF + 127) / 128, TT / TB, NB);
        cfg.blockDim = dim3(128);
        cfg.stream = 0;
        cfg.attrs = attr;
        cfg.numAttrs = 1;
        cudaLaunchKernelEx(&cfg, bf_kernel, mixture, out);
    }
}